// round 12
// baseline (speedup 1.0000x reference)
#include <cuda_runtime.h>
#include <math.h>

// TV loss over x:(3, 4096, 4096) fp32 -> scalar sqrt(sum(dx^2)+sum(dy^2))
// 512-thread blocks (3/SM -> 42-reg budget), 4-row unrolled mainloop for MLP=4,
// one full wave: 2 column stripes x 74 balanced row groups x 3 ch = 444 = 148*3.
// Per-thread sidecar load; atomic+ticket finalize.

#define W 4096
#define H 4096
#define CH 3
#define THREADS 512
#define NSTRIPE 2              // 512 threads * 4 floats = 2048 cols per stripe
#define NGROUPS 74             // 2*74*3 = 444 blocks = 148 SMs * 3 (one wave)
#define NUM_BLOCKS (NSTRIPE * NGROUPS * CH)
#define BASE_ROWS (H - 1)      // base rows 0..4094

__device__ unsigned long long g_acc_bits = 0ull;   // double accumulator as bits
__device__ unsigned int g_count = 0;

// accumulate dx^2 into a0 and dy^2 into a1 for this thread's 4 columns
__device__ __forceinline__ void tv_accum(float& a0, float& a1, const float4& cur,
                                         float curext, const float4& nxt, bool last_col) {
    float d0 = cur.y - cur.x;
    float d1 = cur.z - cur.y;
    float d2 = cur.w - cur.z;
    a0 = fmaf(d0, d0, a0);
    a0 = fmaf(d1, d1, a0);
    a0 = fmaf(d2, d2, a0);
    float e0 = nxt.x - cur.x;
    float e1 = nxt.y - cur.y;
    float e2 = nxt.z - cur.z;
    a1 = fmaf(e0, e0, a1);
    a1 = fmaf(e1, e1, a1);
    a1 = fmaf(e2, e2, a1);
    if (!last_col) {
        float d3 = curext - cur.w;
        float e3 = nxt.w - cur.w;
        a0 = fmaf(d3, d3, a0);
        a1 = fmaf(e3, e3, a1);
    }
}

__global__ __launch_bounds__(THREADS, 3) void tv_fused_kernel(const float* __restrict__ x,
                                                              float* __restrict__ out) {
    const int ch = blockIdx.z;
    const int g  = blockIdx.y;
    const int c4 = (blockIdx.x * THREADS + threadIdx.x) * 4;

    // balanced row range for group g
    const int row0 = (int)(((long long)g * BASE_ROWS) / NGROUPS);
    const int rend = (int)(((long long)(g + 1) * BASE_ROWS) / NGROUPS);

    const float* __restrict__ base = x + (size_t)ch * W * H;
    const bool last_col = (c4 == W - 4);   // j=4095 excluded entirely

    float a0 = 0.0f, a1 = 0.0f;

    const float* p = base + (size_t)row0 * W + c4;
    float4 cur    = *(const float4*)p;
    float  curext = last_col ? 0.0f : p[4];

    // ---- 4-row unrolled mainloop: all four vector loads front-batched ----
    int i = row0;
    const int quad_end = row0 + ((rend - row0) & ~3);
    for (; i < quad_end; i += 4) {
        const float* p1 = base + (size_t)(i + 1) * W + c4;
        const float* p2 = base + (size_t)(i + 2) * W + c4;
        const float* p3 = base + (size_t)(i + 3) * W + c4;
        const float* p4 = base + (size_t)(i + 4) * W + c4;
        float4 n1 = *(const float4*)p1;
        float4 n2 = *(const float4*)p2;
        float4 n3 = *(const float4*)p3;
        float4 n4 = *(const float4*)p4;
        float e1 = last_col ? 0.0f : p1[4];
        float e2 = last_col ? 0.0f : p2[4];
        float e3 = last_col ? 0.0f : p3[4];
        float e4 = last_col ? 0.0f : p4[4];

        tv_accum(a0, a1, cur, curext, n1, last_col);
        tv_accum(a0, a1, n1, e1, n2, last_col);
        tv_accum(a0, a1, n2, e2, n3, last_col);
        tv_accum(a0, a1, n3, e3, n4, last_col);

        cur = n4;
        curext = e4;
    }
    for (; i < rend; ++i) {    // remainder rows (0..3)
        const float* p1 = base + (size_t)(i + 1) * W + c4;
        float4 n1 = *(const float4*)p1;
        float e1 = last_col ? 0.0f : p1[4];
        tv_accum(a0, a1, cur, curext, n1, last_col);
        cur = n1;
        curext = e1;
    }

    float acc = a0 + a1;

    // ---- block reduction ----
    #pragma unroll
    for (int off = 16; off > 0; off >>= 1)
        acc += __shfl_down_sync(0xFFFFFFFFu, acc, off);

    __shared__ float warp_sums[THREADS / 32];
    __shared__ bool is_last;
    const int lane = threadIdx.x & 31;
    const int wid  = threadIdx.x >> 5;
    if (lane == 0) warp_sums[wid] = acc;
    __syncthreads();

    if (wid == 0) {
        float v = (lane < THREADS / 32) ? warp_sums[lane] : 0.0f;
        #pragma unroll
        for (int off = 8; off > 0; off >>= 1)
            v += __shfl_down_sync(0xFFFFFFFFu, v, off);
        if (lane == 0) {
            atomicAdd((double*)&g_acc_bits, (double)v);
            __threadfence();
            unsigned int ticket = atomicInc(&g_count, NUM_BLOCKS - 1);
            is_last = (ticket == NUM_BLOCKS - 1);   // wraps to 0 for next replay
        }
    }
    __syncthreads();

    // Last block finalizes: read+reset accumulator, write sqrt.
    if (is_last && threadIdx.x == 0) {
        unsigned long long bits = atomicExch(&g_acc_bits, 0ull);
        double total = __longlong_as_double(bits);
        out[0] = (float)sqrt(total);
    }
}

extern "C" void kernel_launch(void* const* d_in, const int* in_sizes, int n_in,
                              void* d_out, int out_size) {
    const float* x = (const float*)d_in[0];
    float* out = (float*)d_out;

    dim3 grid(NSTRIPE, NGROUPS, CH);
    tv_fused_kernel<<<grid, THREADS>>>(x, out);
}